// round 16
// baseline (speedup 1.0000x reference)
#include <cuda_runtime.h>
#include <cuda_fp16.h>
#include <math.h>
#include <stdint.h>

#define D_MODEL 2048
#define NH      16
#define DK      128
#define SEQ     2048
#define BATCH   2
#define KDIM    2048
#define MDIM    (BATCH*SEQ)   // 4096

// -------- scratch (static device memory; no cudaMalloc allowed) ------------
__device__ __half g_Q  [BATCH*NH*SEQ*DK];     // [b,h,s,d] post-RoPE, pre-scaled
__device__ __half g_K  [BATCH*NH*SEQ*DK];     // [b,h,s,d] post-RoPE
__device__ __half g_Vt [BATCH*NH*DK*SEQ];     // [b,h,d,s] transposed
__device__ __half g_att[BATCH*SEQ*D_MODEL];   // [b,s,h*128+d]
__device__ __half g_xh [MDIM*KDIM];           // fp16 x
__device__ __half g_wqh[KDIM*KDIM];
__device__ __half g_wkh[KDIM*KDIM];
__device__ __half g_wvh[KDIM*KDIM];
__device__ __half g_woh[KDIM*KDIM];
__device__ float  g_rc [SEQ*64];              // RoPE cos LUT [s][d/2]
__device__ float  g_rs [SEQ*64];              // RoPE sin LUT

// ============================================================================
// helpers
// ============================================================================
__device__ __forceinline__ uint32_t smem_u32(const void* p) {
    uint32_t a;
    asm("{ .reg .u64 t; cvta.to.shared.u64 t, %1; cvt.u32.u64 %0, t; }"
        : "=r"(a) : "l"(p));
    return a;
}

#define CP16(dst, src) \
    asm volatile("cp.async.cg.shared.global [%0], [%1], 16;" \
                 :: "r"(dst), "l"(src) : "memory")
#define CP_COMMIT()  asm volatile("cp.async.commit_group;" ::: "memory")
#define CP_WAIT(n)   asm volatile("cp.async.wait_group %0;" :: "n"(n) : "memory")

#define LDSM_X4(r0, r1, r2, r3, addr) \
    asm volatile("ldmatrix.sync.aligned.m8n8.x4.shared.b16 {%0,%1,%2,%3}, [%4];" \
                 : "=r"(r0), "=r"(r1), "=r"(r2), "=r"(r3) : "r"(addr))

__device__ __forceinline__ void mma_f16(float& d0, float& d1, float& d2, float& d3,
                                        uint32_t a0, uint32_t a1, uint32_t a2, uint32_t a3,
                                        uint32_t b0, uint32_t b1) {
    asm volatile(
        "mma.sync.aligned.m16n8k16.row.col.f32.f16.f16.f32 "
        "{%0,%1,%2,%3}, {%4,%5,%6,%7}, {%8,%9}, {%0,%1,%2,%3};"
        : "+f"(d0), "+f"(d1), "+f"(d2), "+f"(d3)
        : "r"(a0), "r"(a1), "r"(a2), "r"(a3), "r"(b0), "r"(b1));
}

// ============================================================================
// prep: all five fp32 -> fp16 conversions in ONE launch. 8 elems/thread
// (reverted to R14 known-good shape; 16/thread measurably regressed).
// ============================================================================
#define XELEMS  ((size_t)MDIM * KDIM)          // 8M
#define WELEMS  ((size_t)KDIM * KDIM)          // 4M

__global__ void to_half_all(const float* __restrict__ x,
                            const float* __restrict__ wq,
                            const float* __restrict__ wk,
                            const float* __restrict__ wv,
                            const float* __restrict__ wo)
{
    size_t e = ((size_t)blockIdx.x * blockDim.x + threadIdx.x) * 8;
    const float* src;
    __half* dst;
    size_t off;
    if (e < XELEMS) { src = x; dst = g_xh; off = e; }
    else {
        size_t j = e - XELEMS;
        int w = (int)(j / WELEMS);
        off = j - (size_t)w * WELEMS;
        src = (w == 0) ? wq : (w == 1) ? wk : (w == 2) ? wv : wo;
        dst = (w == 0) ? g_wqh : (w == 1) ? g_wkh : (w == 2) ? g_wvh : g_woh;
    }
    float4 v0 = *(const float4*)&src[off];
    float4 v1 = *(const float4*)&src[off + 4];
    __half2 h[4];
    h[0] = __floats2half2_rn(v0.x, v0.y);
    h[1] = __floats2half2_rn(v0.z, v0.w);
    h[2] = __floats2half2_rn(v1.x, v1.y);
    h[3] = __floats2half2_rn(v1.z, v1.w);
    *(uint4*)&dst[off] = *(uint4*)h;
}

// ============================================================================
// prep: RoPE cos/sin LUT
// ============================================================================
__global__ void rope_lut(const int* __restrict__ pos)
{
    int idx = blockIdx.x * 256 + threadIdx.x;   // 0 .. SEQ*64-1
    int s = idx >> 6;
    int j = idx & 63;                            // d = 2j
    float freq = (float)exp(-(double)(2 * j) * (9.210340371976184 / 128.0));
    float p = (float)pos[s];
    double ang = (double)(p * freq);
    double q   = rint(ang * 0.15915494309189535);
    float red  = (float)(ang - q * 6.283185307179586);
    float sn, cs;
    sincosf(red, &sn, &cs);
    g_rc[idx] = cs;
    g_rs[idx] = sn;
}

// ============================================================================
// fp16 mma.sync NT GEMM, ldmatrix fragment loads, 3-stage cp.async pipeline.
// (unchanged — measured at ~100% of the HMMA.F32 issue ceiling)
// CTA tile 256x128, BK=64, 256 thr, 8 warps (4m x 2n), warp tile 64x64.
// MODE 0: fused QKV (grid 48 x 16).  MODE 1: wo (grid 16 x 16) -> fp32 out.
// ============================================================================
#define TSTR    72
#define ATILEH  (256 * TSTR)
#define BTILEH  (128 * TSTR)
#define STAGEH  (ATILEH + BTILEH)       // 27648 halves = 55296 B
#define GEMM_SMEM (3 * STAGEH * 2)      // 165888 B
#define QSCALE 0.08838834764831845f

template<int MODE>
__global__ __launch_bounds__(256, 1) void gemm_mma(float* __restrict__ Cout)
{
    extern __shared__ char smc[];
    __half* smh = (__half*)smc;
    const int tid = threadIdx.x;
    const int wid = tid >> 5;
    const int lane = tid & 31;
    const int g = lane >> 2;
    const int cl = lane & 3;
    const int wm = wid & 3;
    const int wn = wid >> 2;
    const int m0 = blockIdx.y * 256;

    int wsel, hh, n0;
    if (MODE == 0) { wsel = blockIdx.x % 3; hh = blockIdx.x / 3; n0 = hh * 128; }
    else           { wsel = 3; hh = 0; n0 = blockIdx.x * 128; }

    const __half* __restrict__ Ap = (MODE == 0) ? g_xh : g_att;
    const __half* __restrict__ Bp = (MODE == 1) ? g_woh :
                                    (wsel == 0) ? g_wqh :
                                    (wsel == 1) ? g_wkh : g_wvh;
    const __half* __restrict__ arow = Ap + (size_t)m0 * KDIM;
    const __half* __restrict__ brow = Bp + (size_t)n0 * KDIM;

    const uint32_t sb = smem_u32(smc);
    const int ldr = tid >> 3;
    const int ldc = (tid & 7) * 8;

    auto load_tile = [&](int stage, int kt) {
        uint32_t base = sb + stage * STAGEH * 2;
        #pragma unroll
        for (int i = 0; i < 8; i++) {
            int r = ldr + i * 32;
            CP16(base + (r * TSTR + ldc) * 2, &arow[(size_t)r * KDIM + kt + ldc]);
        }
        #pragma unroll
        for (int i = 0; i < 4; i++) {
            int r = ldr + i * 32;
            CP16(base + (ATILEH + r * TSTR + ldc) * 2,
                 &brow[(size_t)r * KDIM + kt + ldc]);
        }
    };

    float acc[4][8][4];
    #pragma unroll
    for (int i = 0; i < 4; i++)
        #pragma unroll
        for (int j = 0; j < 8; j++)
            #pragma unroll
            for (int k = 0; k < 4; k++) acc[i][j][k] = 0.0f;

    load_tile(0, 0);
    CP_COMMIT();
    load_tile(1, 64);
    CP_COMMIT();

    const int lr  = lane & 7;
    const int s8  = (lane >> 3) & 1;
    const int s16 = lane >> 4;
    const uint32_t abase = sb + ((wm * 64 + lr + s8 * 8) * TSTR + s16 * 8) * 2;
    const uint32_t bbase = sb + (ATILEH + (wn * 64 + s16 * 8 + lr) * TSTR + s8 * 8) * 2;

    int stage = 0;
    for (int c = 0; c < 32; c++) {
        if (c < 31) { CP_WAIT(1); } else { CP_WAIT(0); }
        __syncthreads();
        if (c + 2 < 32) {
            int s2 = stage + 2; if (s2 >= 3) s2 -= 3;
            load_tile(s2, (c + 2) * 64);
            CP_COMMIT();
        }

        const uint32_t stg = stage * STAGEH * 2;

        #pragma unroll
        for (int ks = 0; ks < 4; ks++) {
            uint32_t a[4][4], b[8][2];
            #pragma unroll
            for (int mf = 0; mf < 4; mf++)
                LDSM_X4(a[mf][0], a[mf][1], a[mf][2], a[mf][3],
                        abase + stg + (mf * 16 * TSTR + ks * 16) * 2);
            #pragma unroll
            for (int nfp = 0; nfp < 4; nfp++)
                LDSM_X4(b[2*nfp][0], b[2*nfp][1], b[2*nfp+1][0], b[2*nfp+1][1],
                        bbase + stg + (nfp * 16 * TSTR + ks * 16) * 2);
            #pragma unroll
            for (int mf = 0; mf < 4; mf++)
                #pragma unroll
                for (int nf = 0; nf < 8; nf++)
                    mma_f16(acc[mf][nf][0], acc[mf][nf][1],
                            acc[mf][nf][2], acc[mf][nf][3],
                            a[mf][0], a[mf][1], a[mf][2], a[mf][3],
                            b[nf][0], b[nf][1]);
        }
        stage = (stage == 2) ? 0 : stage + 1;
    }

    // ---- epilogues ----
    if (MODE == 1) {
        #pragma unroll
        for (int mf = 0; mf < 4; mf++)
            #pragma unroll
            for (int half = 0; half < 2; half++) {
                int m = m0 + wm * 64 + mf * 16 + g + half * 8;
                float* o = &Cout[(size_t)m * D_MODEL + n0 + wn * 64 + cl * 2];
                #pragma unroll
                for (int nf = 0; nf < 8; nf++)
                    *(float2*)&o[nf * 8] =
                        make_float2(acc[mf][nf][half * 2], acc[mf][nf][half * 2 + 1]);
            }
        return;
    }

    if (wsel == 2) {
        __syncthreads();
        __half* T = smh;                      // 128 d x 264 stride
        #pragma unroll
        for (int mf = 0; mf < 4; mf++)
            #pragma unroll
            for (int half = 0; half < 2; half++) {
                int sl = wm * 64 + mf * 16 + g + half * 8;
                #pragma unroll
                for (int nf = 0; nf < 8; nf++) {
                    int dl = wn * 64 + nf * 8 + cl * 2;
                    T[dl * 264 + sl]       = __float2half_rn(acc[mf][nf][half * 2]);
                    T[(dl + 1) * 264 + sl] = __float2half_rn(acc[mf][nf][half * 2 + 1]);
                }
            }
        __syncthreads();
        const int b = m0 >> 11;
        const int srow0 = m0 & 2047;
        #pragma unroll
        for (int i = 0; i < 16; i++) {
            int idx = tid + i * 256;
            int r   = idx >> 5;
            int c8  = (idx & 31) * 8;
            uint4 v = *(uint4*)&T[r * 264 + c8];
            *(uint4*)&g_Vt[((size_t)((b * NH + hh) * DK + r)) * SEQ + srow0 + c8] = v;
        }
        return;
    }

    __half* dptr = (wsel == 0) ? g_Q : g_K;
    const float qs = (wsel == 0) ? QSCALE : 1.0f;
    #pragma unroll
    for (int mf = 0; mf < 4; mf++)
        #pragma unroll
        for (int half = 0; half < 2; half++) {
            int m = m0 + wm * 64 + mf * 16 + g + half * 8;
            int b = m >> 11;
            int s = m & 2047;
            const float* lc = &g_rc[s * 64 + wn * 32 + cl];
            const float* ls = &g_rs[s * 64 + wn * 32 + cl];
            __half2* o = (__half2*)&dptr[(size_t)((b * NH + hh) * SEQ + s) * DK
                                         + wn * 64 + cl * 2];
            #pragma unroll
            for (int nf = 0; nf < 8; nf++) {
                float cs = lc[nf * 4];
                float sn = ls[nf * 4];
                float e  = acc[mf][nf][half * 2] * qs;
                float od = acc[mf][nf][half * 2 + 1] * qs;
                o[nf * 4] = __floats2half2_rn(e * cs - od * sn, e * sn + od * cs);
            }
        }
}

// ============================================================================
// Flash attention v7 (unchanged from R15 — measured 182.6 us).
// Single barrier per tile: at iteration top only group KV(kt) is pending, so
// CP_WAIT(0)+one barrier publishes KV(kt) AND proves stage (kt+1)&1 free;
// KV(kt+1) prefetches under compute of tile kt.
// Q-tile 128 x kv-tile 64, 8 warps, warp w owns q rows [16w,16w+16).
// smem halves: Qs 128x136 | Ks 2x 64x136 | Vt 2x 128x72  = 106496 B
// ============================================================================
#define FQ   0
#define FKo  (128 * 136)
#define FKS  (64 * 136)
#define FV   (FKo + 2 * FKS)
#define FVS  (128 * 72)
#define FLASH_SMEM ((FV + 2 * FVS) * 2)      // 106496 B
#define L2E 1.4426950408889634f

__global__ __launch_bounds__(256, 2) void flash_mma()
{
    extern __shared__ char smc[];
    __half* smh = (__half*)smc;
    const uint32_t sb = smem_u32(smc);

    const int tid  = threadIdx.x;
    const int w    = tid >> 5;
    const int lane = tid & 31;
    const int g    = lane >> 2;
    const int cl   = lane & 3;
    const int qt   = (gridDim.x - 1) - blockIdx.x;   // heavy tiles first
    const int bh   = blockIdx.y;
    const int q0   = qt * 128;
    const int wrow = w * 16;

    auto issue_Q = [&]() {
        #pragma unroll
        for (int i = 0; i < 8; i++) {
            int idx = tid + i * 256;
            int r = idx >> 4, c8 = (idx & 15) * 8;
            CP16(sb + (r * 136 + c8) * 2,
                 &g_Q[(size_t)(bh * SEQ + q0 + r) * DK + c8]);
        }
    };
    auto issue_KV = [&](int kt) {
        int st = kt & 1, k0 = kt * 64;
        #pragma unroll
        for (int i = 0; i < 4; i++) {
            int idx = tid + i * 256;
            int r = idx >> 4, c8 = (idx & 15) * 8;
            CP16(sb + (FKo + st * FKS + r * 136 + c8) * 2,
                 &g_K[(size_t)(bh * SEQ + k0 + r) * DK + c8]);
        }
        #pragma unroll
        for (int i = 0; i < 4; i++) {
            int idx = tid + i * 256;
            int d = idx >> 3, c8 = (idx & 7) * 8;
            CP16(sb + (FV + st * FVS + d * 72 + c8) * 2,
                 &g_Vt[((size_t)bh * DK + d) * SEQ + k0 + c8]);
        }
    };

    issue_KV(0);
    issue_Q();
    CP_COMMIT();

    float oacc[16][4];
    #pragma unroll
    for (int i = 0; i < 16; i++)
        #pragma unroll
        for (int k = 0; k < 4; k++) oacc[i][k] = 0.0f;
    float mrow[2] = {-INFINITY, -INFINITY};
    float lrow[2] = {0.0f, 0.0f};

    const int lr  = lane & 7;
    const int s8  = (lane >> 3) & 1;
    const int s16 = lane >> 4;
    const uint32_t qlane  = sb + ((wrow + lr + s8 * 8) * 136 + s16 * 8) * 2;
    const uint32_t klane0 = sb + ((s16 * 8 + lr) * 136 + s8 * 8) * 2;
    const uint32_t vlane0 = sb + ((s16 * 8 + lr) * 72 + s8 * 8) * 2;

    const int ktiles = 2 * qt + 2;
    for (int kt = 0; kt < ktiles; kt++) {
        const int k0 = kt * 64;

        CP_WAIT(0);                  // only group KV(kt) is pending
        __syncthreads();             // publish KV(kt); stage (kt+1)&1 is free
        if (kt + 1 < ktiles) { issue_KV(kt + 1); CP_COMMIT(); }

        // full-mask skip: this warp's rows all above diagonal -> bit-identical
        if (k0 > q0 + wrow + 15) continue;

        const uint32_t kbase = klane0 + (FKo + (kt & 1) * FKS) * 2;
        const uint32_t vbase = vlane0 + (FV  + (kt & 1) * FVS) * 2;

        // ---- S = Q K^T ----
        float sacc[8][4];
        #pragma unroll
        for (int nf = 0; nf < 8; nf++)
            #pragma unroll
            for (int k = 0; k < 4; k++) sacc[nf][k] = 0.0f;

        #pragma unroll
        for (int ks = 0; ks < 8; ks++) {
            uint32_t a0, a1, a2, a3;
            LDSM_X4(a0, a1, a2, a3, qlane + ks * 32);
            #pragma unroll
            for (int nfp = 0; nfp < 4; nfp++) {
                uint32_t b0, b1, b2, b3;
                LDSM_X4(b0, b1, b2, b3, kbase + (nfp * 16 * 136 + ks * 16) * 2);
                mma_f16(sacc[2*nfp][0], sacc[2*nfp][1], sacc[2*nfp][2], sacc[2*nfp][3],
                        a0, a1, a2, a3, b0, b1);
                mma_f16(sacc[2*nfp+1][0], sacc[2*nfp+1][1], sacc[2*nfp+1][2], sacc[2*nfp+1][3],
                        a0, a1, a2, a3, b2, b3);
            }
        }

        // ---- causal mask (partial tiles only) ----
        if (k0 + 63 > q0 + wrow) {
            #pragma unroll
            for (int nf = 0; nf < 8; nf++)
                #pragma unroll
                for (int k = 0; k < 4; k++) {
                    int row = q0 + wrow + g + (k >> 1) * 8;
                    int col = k0 + nf * 8 + cl * 2 + (k & 1);
                    if (col > row) sacc[nf][k] = -INFINITY;
                }
        }

        // ---- online softmax, both row-halves interleaved ----
        uint32_t pa[4][4];
        {
            float mt0 = -INFINITY, mt1 = -INFINITY;
            #pragma unroll
            for (int nf = 0; nf < 8; nf++) {
                mt0 = fmaxf(mt0, fmaxf(sacc[nf][0], sacc[nf][1]));
                mt1 = fmaxf(mt1, fmaxf(sacc[nf][2], sacc[nf][3]));
            }
            mt0 = fmaxf(mt0, __shfl_xor_sync(0xffffffffu, mt0, 1));
            mt1 = fmaxf(mt1, __shfl_xor_sync(0xffffffffu, mt1, 1));
            mt0 = fmaxf(mt0, __shfl_xor_sync(0xffffffffu, mt0, 2));
            mt1 = fmaxf(mt1, __shfl_xor_sync(0xffffffffu, mt1, 2));
            float mnew0 = fmaxf(mrow[0], mt0);
            float mnew1 = fmaxf(mrow[1], mt1);
            float alpha0 = exp2f((mrow[0] - mnew0) * L2E);
            float alpha1 = exp2f((mrow[1] - mnew1) * L2E);
            float psum0 = 0.0f, psum1 = 0.0f;
            #pragma unroll
            for (int nf = 0; nf < 8; nf++) {
                float p00 = exp2f((sacc[nf][0] - mnew0) * L2E);
                float p01 = exp2f((sacc[nf][1] - mnew0) * L2E);
                float p10 = exp2f((sacc[nf][2] - mnew1) * L2E);
                float p11 = exp2f((sacc[nf][3] - mnew1) * L2E);
                psum0 += p00 + p01;
                psum1 += p10 + p11;
                __half2 ph0 = __floats2half2_rn(p00, p01);
                __half2 ph1 = __floats2half2_rn(p10, p11);
                pa[nf >> 1][(nf & 1) * 2 + 0] = *(uint32_t*)&ph0;
                pa[nf >> 1][(nf & 1) * 2 + 1] = *(uint32_t*)&ph1;
            }
            psum0 += __shfl_xor_sync(0xffffffffu, psum0, 1);
            psum1 += __shfl_xor_sync(0xffffffffu, psum1, 1);
            psum0 += __shfl_xor_sync(0xffffffffu, psum0, 2);
            psum1 += __shfl_xor_sync(0xffffffffu, psum1, 2);
            lrow[0] = lrow[0] * alpha0 + psum0;
            lrow[1] = lrow[1] * alpha1 + psum1;
            mrow[0] = mnew0;
            mrow[1] = mnew1;
            #pragma unroll
            for (int nf2 = 0; nf2 < 16; nf2++) {
                oacc[nf2][0] *= alpha0;
                oacc[nf2][1] *= alpha0;
                oacc[nf2][2] *= alpha1;
                oacc[nf2][3] *= alpha1;
            }
        }

        // ---- O += P * V  (P from registers) ----
        #pragma unroll
        for (int j = 0; j < 4; j++) {
            #pragma unroll
            for (int nfp = 0; nfp < 8; nfp++) {
                uint32_t b0, b1, b2, b3;
                LDSM_X4(b0, b1, b2, b3, vbase + (nfp * 16 * 72 + j * 16) * 2);
                mma_f16(oacc[2*nfp][0], oacc[2*nfp][1], oacc[2*nfp][2], oacc[2*nfp][3],
                        pa[j][0], pa[j][1], pa[j][2], pa[j][3], b0, b1);
                mma_f16(oacc[2*nfp+1][0], oacc[2*nfp+1][1], oacc[2*nfp+1][2], oacc[2*nfp+1][3],
                        pa[j][0], pa[j][1], pa[j][2], pa[j][3], b2, b3);
            }
        }
    }

    // ---- epilogue: scale by 1/l, store half (feeds wo GEMM) ----
    const int b  = bh >> 4;
    const int hh = bh & 15;
    #pragma unroll
    for (int h = 0; h < 2; h++) {
        float inv = 1.0f / lrow[h];
        int row = q0 + wrow + g + h * 8;
        __half2* o = (__half2*)&g_att[(size_t)(b * SEQ + row) * D_MODEL
                                      + hh * DK + cl * 2];
        #pragma unroll
        for (int nf2 = 0; nf2 < 16; nf2++)
            o[nf2 * 4] = __floats2half2_rn(oacc[nf2][h * 2]     * inv,
                                           oacc[nf2][h * 2 + 1] * inv);
    }
}

// ============================================================================
extern "C" void kernel_launch(void* const* d_in, const int* in_sizes, int n_in,
                              void* d_out, int out_size)
{
    const float* x   = (const float*)d_in[0];
    const float* wq  = (const float*)d_in[1];
    const float* wk  = (const float*)d_in[2];
    const float* wv  = (const float*)d_in[3];
    const float* wo  = (const float*)d_in[4];
    const int*   pos = (const int*)  d_in[5];
    float* out = (float*)d_out;

    cudaFuncSetAttribute(gemm_mma<0>, cudaFuncAttributeMaxDynamicSharedMemorySize,
                         GEMM_SMEM);
    cudaFuncSetAttribute(gemm_mma<1>, cudaFuncAttributeMaxDynamicSharedMemorySize,
                         GEMM_SMEM);
    cudaFuncSetAttribute(flash_mma, cudaFuncAttributeMaxDynamicSharedMemorySize,
                         FLASH_SMEM);

    // 24M elems / 8 per thread / 256 per block = 12288 blocks
    to_half_all<<<12288, 256>>>(x, wq, wk, wv, wo);
    rope_lut<<<(SEQ*64)/256, 256>>>(pos);

    gemm_mma<0><<<dim3(48, MDIM/256), 256, GEMM_SMEM>>>(nullptr);      // QKV
    flash_mma<<<dim3(SEQ/128, BATCH*NH), 256, FLASH_SMEM>>>();
    gemm_mma<1><<<dim3(D_MODEL/128, MDIM/256), 256, GEMM_SMEM>>>(out); // wo
}

// round 17
// speedup vs baseline: 1.0265x; 1.0265x over previous
#include <cuda_runtime.h>
#include <cuda_fp16.h>
#include <math.h>
#include <stdint.h>

#define D_MODEL 2048
#define NH      16
#define DK      128
#define SEQ     2048
#define BATCH   2
#define KDIM    2048
#define MDIM    (BATCH*SEQ)   // 4096

// -------- scratch (static device memory; no cudaMalloc allowed) ------------
__device__ __half g_Q  [BATCH*NH*SEQ*DK];     // [b,h,s,d] post-RoPE, pre-scaled
__device__ __half g_K  [BATCH*NH*SEQ*DK];     // [b,h,s,d] post-RoPE
__device__ __half g_Vt [BATCH*NH*DK*SEQ];     // [b,h,d,s] transposed
__device__ __half g_att[BATCH*SEQ*D_MODEL];   // [b,s,h*128+d]
__device__ __half g_xh [MDIM*KDIM];           // fp16 x
__device__ __half g_wqh[KDIM*KDIM];
__device__ __half g_wkh[KDIM*KDIM];
__device__ __half g_wvh[KDIM*KDIM];
__device__ __half g_woh[KDIM*KDIM];
__device__ float  g_rc [SEQ*64];              // RoPE cos LUT [s][d/2]
__device__ float  g_rs [SEQ*64];              // RoPE sin LUT

// ============================================================================
// helpers
// ============================================================================
__device__ __forceinline__ uint32_t smem_u32(const void* p) {
    uint32_t a;
    asm("{ .reg .u64 t; cvta.to.shared.u64 t, %1; cvt.u32.u64 %0, t; }"
        : "=r"(a) : "l"(p));
    return a;
}

#define CP16(dst, src) \
    asm volatile("cp.async.cg.shared.global [%0], [%1], 16;" \
                 :: "r"(dst), "l"(src) : "memory")
#define CP_COMMIT()  asm volatile("cp.async.commit_group;" ::: "memory")
#define CP_WAIT(n)   asm volatile("cp.async.wait_group %0;" :: "n"(n) : "memory")

#define LDSM_X4(r0, r1, r2, r3, addr) \
    asm volatile("ldmatrix.sync.aligned.m8n8.x4.shared.b16 {%0,%1,%2,%3}, [%4];" \
                 : "=r"(r0), "=r"(r1), "=r"(r2), "=r"(r3) : "r"(addr))

__device__ __forceinline__ void mma_f16(float& d0, float& d1, float& d2, float& d3,
                                        uint32_t a0, uint32_t a1, uint32_t a2, uint32_t a3,
                                        uint32_t b0, uint32_t b1) {
    asm volatile(
        "mma.sync.aligned.m16n8k16.row.col.f32.f16.f16.f32 "
        "{%0,%1,%2,%3}, {%4,%5,%6,%7}, {%8,%9}, {%0,%1,%2,%3};"
        : "+f"(d0), "+f"(d1), "+f"(d2), "+f"(d3)
        : "r"(a0), "r"(a1), "r"(a2), "r"(a3), "r"(b0), "r"(b1));
}

// ============================================================================
// prep: all five fp32 -> fp16 conversions in ONE launch. 8 elems/thread.
// ============================================================================
#define XELEMS  ((size_t)MDIM * KDIM)          // 8M
#define WELEMS  ((size_t)KDIM * KDIM)          // 4M

__global__ void to_half_all(const float* __restrict__ x,
                            const float* __restrict__ wq,
                            const float* __restrict__ wk,
                            const float* __restrict__ wv,
                            const float* __restrict__ wo)
{
    size_t e = ((size_t)blockIdx.x * blockDim.x + threadIdx.x) * 8;
    const float* src;
    __half* dst;
    size_t off;
    if (e < XELEMS) { src = x; dst = g_xh; off = e; }
    else {
        size_t j = e - XELEMS;
        int w = (int)(j / WELEMS);
        off = j - (size_t)w * WELEMS;
        src = (w == 0) ? wq : (w == 1) ? wk : (w == 2) ? wv : wo;
        dst = (w == 0) ? g_wqh : (w == 1) ? g_wkh : (w == 2) ? g_wvh : g_woh;
    }
    float4 v0 = *(const float4*)&src[off];
    float4 v1 = *(const float4*)&src[off + 4];
    __half2 h[4];
    h[0] = __floats2half2_rn(v0.x, v0.y);
    h[1] = __floats2half2_rn(v0.z, v0.w);
    h[2] = __floats2half2_rn(v1.x, v1.y);
    h[3] = __floats2half2_rn(v1.z, v1.w);
    *(uint4*)&dst[off] = *(uint4*)h;
}

// ============================================================================
// prep: RoPE cos/sin LUT
// ============================================================================
__global__ void rope_lut(const int* __restrict__ pos)
{
    int idx = blockIdx.x * 256 + threadIdx.x;   // 0 .. SEQ*64-1
    int s = idx >> 6;
    int j = idx & 63;                            // d = 2j
    float freq = (float)exp(-(double)(2 * j) * (9.210340371976184 / 128.0));
    float p = (float)pos[s];
    double ang = (double)(p * freq);
    double q   = rint(ang * 0.15915494309189535);
    float red  = (float)(ang - q * 6.283185307179586);
    float sn, cs;
    sincosf(red, &sn, &cs);
    g_rc[idx] = cs;
    g_rs[idx] = sn;
}

// ============================================================================
// fp16 mma.sync NT GEMM, ldmatrix fragment loads, 3-stage cp.async pipeline.
// (unchanged — measured at ~100% of the HMMA.F32 issue ceiling)
// CTA tile 256x128, BK=64, 256 thr, 8 warps (4m x 2n), warp tile 64x64.
// MODE 0: fused QKV (grid 48 x 16).  MODE 1: wo (grid 16 x 16) -> fp32 out.
// ============================================================================
#define TSTR    72
#define ATILEH  (256 * TSTR)
#define BTILEH  (128 * TSTR)
#define STAGEH  (ATILEH + BTILEH)       // 27648 halves = 55296 B
#define GEMM_SMEM (3 * STAGEH * 2)      // 165888 B
#define QSCALE 0.08838834764831845f

template<int MODE>
__global__ __launch_bounds__(256, 1) void gemm_mma(float* __restrict__ Cout)
{
    extern __shared__ char smc[];
    __half* smh = (__half*)smc;
    const int tid = threadIdx.x;
    const int wid = tid >> 5;
    const int lane = tid & 31;
    const int g = lane >> 2;
    const int cl = lane & 3;
    const int wm = wid & 3;
    const int wn = wid >> 2;
    const int m0 = blockIdx.y * 256;

    int wsel, hh, n0;
    if (MODE == 0) { wsel = blockIdx.x % 3; hh = blockIdx.x / 3; n0 = hh * 128; }
    else           { wsel = 3; hh = 0; n0 = blockIdx.x * 128; }

    const __half* __restrict__ Ap = (MODE == 0) ? g_xh : g_att;
    const __half* __restrict__ Bp = (MODE == 1) ? g_woh :
                                    (wsel == 0) ? g_wqh :
                                    (wsel == 1) ? g_wkh : g_wvh;
    const __half* __restrict__ arow = Ap + (size_t)m0 * KDIM;
    const __half* __restrict__ brow = Bp + (size_t)n0 * KDIM;

    const uint32_t sb = smem_u32(smc);
    const int ldr = tid >> 3;
    const int ldc = (tid & 7) * 8;

    auto load_tile = [&](int stage, int kt) {
        uint32_t base = sb + stage * STAGEH * 2;
        #pragma unroll
        for (int i = 0; i < 8; i++) {
            int r = ldr + i * 32;
            CP16(base + (r * TSTR + ldc) * 2, &arow[(size_t)r * KDIM + kt + ldc]);
        }
        #pragma unroll
        for (int i = 0; i < 4; i++) {
            int r = ldr + i * 32;
            CP16(base + (ATILEH + r * TSTR + ldc) * 2,
                 &brow[(size_t)r * KDIM + kt + ldc]);
        }
    };

    float acc[4][8][4];
    #pragma unroll
    for (int i = 0; i < 4; i++)
        #pragma unroll
        for (int j = 0; j < 8; j++)
            #pragma unroll
            for (int k = 0; k < 4; k++) acc[i][j][k] = 0.0f;

    load_tile(0, 0);
    CP_COMMIT();
    load_tile(1, 64);
    CP_COMMIT();

    const int lr  = lane & 7;
    const int s8  = (lane >> 3) & 1;
    const int s16 = lane >> 4;
    const uint32_t abase = sb + ((wm * 64 + lr + s8 * 8) * TSTR + s16 * 8) * 2;
    const uint32_t bbase = sb + (ATILEH + (wn * 64 + s16 * 8 + lr) * TSTR + s8 * 8) * 2;

    int stage = 0;
    for (int c = 0; c < 32; c++) {
        if (c < 31) { CP_WAIT(1); } else { CP_WAIT(0); }
        __syncthreads();
        if (c + 2 < 32) {
            int s2 = stage + 2; if (s2 >= 3) s2 -= 3;
            load_tile(s2, (c + 2) * 64);
            CP_COMMIT();
        }

        const uint32_t stg = stage * STAGEH * 2;

        #pragma unroll
        for (int ks = 0; ks < 4; ks++) {
            uint32_t a[4][4], b[8][2];
            #pragma unroll
            for (int mf = 0; mf < 4; mf++)
                LDSM_X4(a[mf][0], a[mf][1], a[mf][2], a[mf][3],
                        abase + stg + (mf * 16 * TSTR + ks * 16) * 2);
            #pragma unroll
            for (int nfp = 0; nfp < 4; nfp++)
                LDSM_X4(b[2*nfp][0], b[2*nfp][1], b[2*nfp+1][0], b[2*nfp+1][1],
                        bbase + stg + (nfp * 16 * TSTR + ks * 16) * 2);
            #pragma unroll
            for (int mf = 0; mf < 4; mf++)
                #pragma unroll
                for (int nf = 0; nf < 8; nf++)
                    mma_f16(acc[mf][nf][0], acc[mf][nf][1],
                            acc[mf][nf][2], acc[mf][nf][3],
                            a[mf][0], a[mf][1], a[mf][2], a[mf][3],
                            b[nf][0], b[nf][1]);
        }
        stage = (stage == 2) ? 0 : stage + 1;
    }

    // ---- epilogues ----
    if (MODE == 1) {
        #pragma unroll
        for (int mf = 0; mf < 4; mf++)
            #pragma unroll
            for (int half = 0; half < 2; half++) {
                int m = m0 + wm * 64 + mf * 16 + g + half * 8;
                float* o = &Cout[(size_t)m * D_MODEL + n0 + wn * 64 + cl * 2];
                #pragma unroll
                for (int nf = 0; nf < 8; nf++)
                    *(float2*)&o[nf * 8] =
                        make_float2(acc[mf][nf][half * 2], acc[mf][nf][half * 2 + 1]);
            }
        return;
    }

    if (wsel == 2) {
        __syncthreads();
        __half* T = smh;                      // 128 d x 264 stride
        #pragma unroll
        for (int mf = 0; mf < 4; mf++)
            #pragma unroll
            for (int half = 0; half < 2; half++) {
                int sl = wm * 64 + mf * 16 + g + half * 8;
                #pragma unroll
                for (int nf = 0; nf < 8; nf++) {
                    int dl = wn * 64 + nf * 8 + cl * 2;
                    T[dl * 264 + sl]       = __float2half_rn(acc[mf][nf][half * 2]);
                    T[(dl + 1) * 264 + sl] = __float2half_rn(acc[mf][nf][half * 2 + 1]);
                }
            }
        __syncthreads();
        const int b = m0 >> 11;
        const int srow0 = m0 & 2047;
        #pragma unroll
        for (int i = 0; i < 16; i++) {
            int idx = tid + i * 256;
            int r   = idx >> 5;
            int c8  = (idx & 31) * 8;
            uint4 v = *(uint4*)&T[r * 264 + c8];
            *(uint4*)&g_Vt[((size_t)((b * NH + hh) * DK + r)) * SEQ + srow0 + c8] = v;
        }
        return;
    }

    __half* dptr = (wsel == 0) ? g_Q : g_K;
    const float qs = (wsel == 0) ? QSCALE : 1.0f;
    #pragma unroll
    for (int mf = 0; mf < 4; mf++)
        #pragma unroll
        for (int half = 0; half < 2; half++) {
            int m = m0 + wm * 64 + mf * 16 + g + half * 8;
            int b = m >> 11;
            int s = m & 2047;
            const float* lc = &g_rc[s * 64 + wn * 32 + cl];
            const float* ls = &g_rs[s * 64 + wn * 32 + cl];
            __half2* o = (__half2*)&dptr[(size_t)((b * NH + hh) * SEQ + s) * DK
                                         + wn * 64 + cl * 2];
            #pragma unroll
            for (int nf = 0; nf < 8; nf++) {
                float cs = lc[nf * 4];
                float sn = ls[nf * 4];
                float e  = acc[mf][nf][half * 2] * qs;
                float od = acc[mf][nf][half * 2 + 1] * qs;
                o[nf * 4] = __floats2half2_rn(e * cs - od * sn, e * sn + od * cs);
            }
        }
}

// ============================================================================
// Flash attention v8: Q FRAGMENTS IN REGISTERS (loaded once via LDSM after
// the prologue) — removes 8 Q-LDSM.x4 per warp per tile (~25% of LDSM
// traffic) and the Q-load dependency at the head of every QK chain.
// Occupancy drops to 1 (regs ~165) — measured-free (R9 occ1 == R10 occ2).
// Loop keeps R16's single top-of-loop barrier (safe with full-mask continue).
// smem halves: Qs 128x136 | Ks 2x 64x136 | Vt 2x 128x72  = 106496 B
// ============================================================================
#define FQ   0
#define FKo  (128 * 136)
#define FKS  (64 * 136)
#define FV   (FKo + 2 * FKS)
#define FVS  (128 * 72)
#define FLASH_SMEM ((FV + 2 * FVS) * 2)      // 106496 B
#define L2E 1.4426950408889634f

__global__ __launch_bounds__(256, 1) void flash_mma()
{
    extern __shared__ char smc[];
    __half* smh = (__half*)smc;
    const uint32_t sb = smem_u32(smc);

    const int tid  = threadIdx.x;
    const int w    = tid >> 5;
    const int lane = tid & 31;
    const int g    = lane >> 2;
    const int cl   = lane & 3;
    const int qt   = (gridDim.x - 1) - blockIdx.x;   // heavy tiles first
    const int bh   = blockIdx.y;
    const int q0   = qt * 128;
    const int wrow = w * 16;

    auto issue_Q = [&]() {
        #pragma unroll
        for (int i = 0; i < 8; i++) {
            int idx = tid + i * 256;
            int r = idx >> 4, c8 = (idx & 15) * 8;
            CP16(sb + (r * 136 + c8) * 2,
                 &g_Q[(size_t)(bh * SEQ + q0 + r) * DK + c8]);
        }
    };
    auto issue_KV = [&](int kt) {
        int st = kt & 1, k0 = kt * 64;
        #pragma unroll
        for (int i = 0; i < 4; i++) {
            int idx = tid + i * 256;
            int r = idx >> 4, c8 = (idx & 15) * 8;
            CP16(sb + (FKo + st * FKS + r * 136 + c8) * 2,
                 &g_K[(size_t)(bh * SEQ + k0 + r) * DK + c8]);
        }
        #pragma unroll
        for (int i = 0; i < 4; i++) {
            int idx = tid + i * 256;
            int d = idx >> 3, c8 = (idx & 7) * 8;
            CP16(sb + (FV + st * FVS + d * 72 + c8) * 2,
                 &g_Vt[((size_t)bh * DK + d) * SEQ + k0 + c8]);
        }
    };

    issue_KV(0);
    issue_Q();
    CP_COMMIT();

    const int lr  = lane & 7;
    const int s8  = (lane >> 3) & 1;
    const int s16 = lane >> 4;
    const uint32_t qlane  = sb + ((wrow + lr + s8 * 8) * 136 + s16 * 8) * 2;
    const uint32_t klane0 = sb + ((s16 * 8 + lr) * 136 + s8 * 8) * 2;
    const uint32_t vlane0 = sb + ((s16 * 8 + lr) * 72 + s8 * 8) * 2;

    // ---- prologue: KV(0) + Q resident; hoist Q fragments into registers ----
    CP_WAIT(0);
    __syncthreads();
    uint32_t qreg[8][4];
    #pragma unroll
    for (int ks = 0; ks < 8; ks++)
        LDSM_X4(qreg[ks][0], qreg[ks][1], qreg[ks][2], qreg[ks][3],
                qlane + ks * 32);

    float oacc[16][4];
    #pragma unroll
    for (int i = 0; i < 16; i++)
        #pragma unroll
        for (int k = 0; k < 4; k++) oacc[i][k] = 0.0f;
    float mrow[2] = {-INFINITY, -INFINITY};
    float lrow[2] = {0.0f, 0.0f};

    const int ktiles = 2 * qt + 2;
    for (int kt = 0; kt < ktiles; kt++) {
        const int k0 = kt * 64;

        CP_WAIT(0);                  // only group KV(kt) can be pending
        __syncthreads();             // publish KV(kt); stage (kt+1)&1 is free
        if (kt + 1 < ktiles) { issue_KV(kt + 1); CP_COMMIT(); }

        // full-mask skip: this warp's rows all above diagonal -> bit-identical
        if (k0 > q0 + wrow + 15) continue;

        const uint32_t kbase = klane0 + (FKo + (kt & 1) * FKS) * 2;
        const uint32_t vbase = vlane0 + (FV  + (kt & 1) * FVS) * 2;

        // ---- S = Q K^T  (Q from registers) ----
        float sacc[8][4];
        #pragma unroll
        for (int nf = 0; nf < 8; nf++)
            #pragma unroll
            for (int k = 0; k < 4; k++) sacc[nf][k] = 0.0f;

        #pragma unroll
        for (int ks = 0; ks < 8; ks++) {
            #pragma unroll
            for (int nfp = 0; nfp < 4; nfp++) {
                uint32_t b0, b1, b2, b3;
                LDSM_X4(b0, b1, b2, b3, kbase + (nfp * 16 * 136 + ks * 16) * 2);
                mma_f16(sacc[2*nfp][0], sacc[2*nfp][1], sacc[2*nfp][2], sacc[2*nfp][3],
                        qreg[ks][0], qreg[ks][1], qreg[ks][2], qreg[ks][3], b0, b1);
                mma_f16(sacc[2*nfp+1][0], sacc[2*nfp+1][1], sacc[2*nfp+1][2], sacc[2*nfp+1][3],
                        qreg[ks][0], qreg[ks][1], qreg[ks][2], qreg[ks][3], b2, b3);
            }
        }

        // ---- causal mask (partial tiles only) ----
        if (k0 + 63 > q0 + wrow) {
            #pragma unroll
            for (int nf = 0; nf < 8; nf++)
                #pragma unroll
                for (int k = 0; k < 4; k++) {
                    int row = q0 + wrow + g + (k >> 1) * 8;
                    int col = k0 + nf * 8 + cl * 2 + (k & 1);
                    if (col > row) sacc[nf][k] = -INFINITY;
                }
        }

        // ---- online softmax, both row-halves interleaved ----
        uint32_t pa[4][4];
        {
            float mt0 = -INFINITY, mt1 = -INFINITY;
            #pragma unroll
            for (int nf = 0; nf < 8; nf++) {
                mt0 = fmaxf(mt0, fmaxf(sacc[nf][0], sacc[nf][1]));
                mt1 = fmaxf(mt1, fmaxf(sacc[nf][2], sacc[nf][3]));
            }
            mt0 = fmaxf(mt0, __shfl_xor_sync(0xffffffffu, mt0, 1));
            mt1 = fmaxf(mt1, __shfl_xor_sync(0xffffffffu, mt1, 1));
            mt0 = fmaxf(mt0, __shfl_xor_sync(0xffffffffu, mt0, 2));
            mt1 = fmaxf(mt1, __shfl_xor_sync(0xffffffffu, mt1, 2));
            float mnew0 = fmaxf(mrow[0], mt0);
            float mnew1 = fmaxf(mrow[1], mt1);
            float alpha0 = exp2f((mrow[0] - mnew0) * L2E);
            float alpha1 = exp2f((mrow[1] - mnew1) * L2E);
            float psum0 = 0.0f, psum1 = 0.0f;
            #pragma unroll
            for (int nf = 0; nf < 8; nf++) {
                float p00 = exp2f((sacc[nf][0] - mnew0) * L2E);
                float p01 = exp2f((sacc[nf][1] - mnew0) * L2E);
                float p10 = exp2f((sacc[nf][2] - mnew1) * L2E);
                float p11 = exp2f((sacc[nf][3] - mnew1) * L2E);
                psum0 += p00 + p01;
                psum1 += p10 + p11;
                __half2 ph0 = __floats2half2_rn(p00, p01);
                __half2 ph1 = __floats2half2_rn(p10, p11);
                pa[nf >> 1][(nf & 1) * 2 + 0] = *(uint32_t*)&ph0;
                pa[nf >> 1][(nf & 1) * 2 + 1] = *(uint32_t*)&ph1;
            }
            psum0 += __shfl_xor_sync(0xffffffffu, psum0, 1);
            psum1 += __shfl_xor_sync(0xffffffffu, psum1, 1);
            psum0 += __shfl_xor_sync(0xffffffffu, psum0, 2);
            psum1 += __shfl_xor_sync(0xffffffffu, psum1, 2);
            lrow[0] = lrow[0] * alpha0 + psum0;
            lrow[1] = lrow[1] * alpha1 + psum1;
            mrow[0] = mnew0;
            mrow[1] = mnew1;
            #pragma unroll
            for (int nf2 = 0; nf2 < 16; nf2++) {
                oacc[nf2][0] *= alpha0;
                oacc[nf2][1] *= alpha0;
                oacc[nf2][2] *= alpha1;
                oacc[nf2][3] *= alpha1;
            }
        }

        // ---- O += P * V  (P from registers) ----
        #pragma unroll
        for (int j = 0; j < 4; j++) {
            #pragma unroll
            for (int nfp = 0; nfp < 8; nfp++) {
                uint32_t b0, b1, b2, b3;
                LDSM_X4(b0, b1, b2, b3, vbase + (nfp * 16 * 72 + j * 16) * 2);
                mma_f16(oacc[2*nfp][0], oacc[2*nfp][1], oacc[2*nfp][2], oacc[2*nfp][3],
                        pa[j][0], pa[j][1], pa[j][2], pa[j][3], b0, b1);
                mma_f16(oacc[2*nfp+1][0], oacc[2*nfp+1][1], oacc[2*nfp+1][2], oacc[2*nfp+1][3],
                        pa[j][0], pa[j][1], pa[j][2], pa[j][3], b2, b3);
            }
        }
    }

    // ---- epilogue: scale by 1/l, store half (feeds wo GEMM) ----
    const int b  = bh >> 4;
    const int hh = bh & 15;
    #pragma unroll
    for (int h = 0; h < 2; h++) {
        float inv = 1.0f / lrow[h];
        int row = q0 + wrow + g + h * 8;
        __half2* o = (__half2*)&g_att[(size_t)(b * SEQ + row) * D_MODEL
                                      + hh * DK + cl * 2];
        #pragma unroll
        for (int nf2 = 0; nf2 < 16; nf2++)
            o[nf2 * 4] = __floats2half2_rn(oacc[nf2][h * 2]     * inv,
                                           oacc[nf2][h * 2 + 1] * inv);
    }
}

// ============================================================================
extern "C" void kernel_launch(void* const* d_in, const int* in_sizes, int n_in,
                              void* d_out, int out_size)
{
    const float* x   = (const float*)d_in[0];
    const float* wq  = (const float*)d_in[1];
    const float* wk  = (const float*)d_in[2];
    const float* wv  = (const float*)d_in[3];
    const float* wo  = (const float*)d_in[4];
    const int*   pos = (const int*)  d_in[5];
    float* out = (float*)d_out;

    cudaFuncSetAttribute(gemm_mma<0>, cudaFuncAttributeMaxDynamicSharedMemorySize,
                         GEMM_SMEM);
    cudaFuncSetAttribute(gemm_mma<1>, cudaFuncAttributeMaxDynamicSharedMemorySize,
                         GEMM_SMEM);
    cudaFuncSetAttribute(flash_mma, cudaFuncAttributeMaxDynamicSharedMemorySize,
                         FLASH_SMEM);

    // 24M elems / 8 per thread / 256 per block = 12288 blocks
    to_half_all<<<12288, 256>>>(x, wq, wk, wv, wo);
    rope_lut<<<(SEQ*64)/256, 256>>>(pos);

    gemm_mma<0><<<dim3(48, MDIM/256), 256, GEMM_SMEM>>>(nullptr);      // QKV
    flash_mma<<<dim3(SEQ/128, BATCH*NH), 256, FLASH_SMEM>>>();
    gemm_mma<1><<<dim3(D_MODEL/128, MDIM/256), 256, GEMM_SMEM>>>(out); // wo
}